// round 4
// baseline (speedup 1.0000x reference)
#include <cuda_runtime.h>
#include <math.h>
#include <stdint.h>

// ---------------- problem constants ----------------
#define QLEN   512
#define MEMLEN 512
#define KLEN   1024
#define BSZ    8
#define NH     16
#define DH     64
#define DM     1024
#define DI     4096
#define NL     6
#define NTOK   32000
#define HD     1024
#define ROWS   (QLEN*BSZ)   // 4096
#define KROWS  (KLEN*BSZ)   // 8192
#define SCALE  0.125f

// ---------------- scratch ----------------
__device__ float g_core [ROWS  * DM];
__device__ float g_qrw  [ROWS  * DM];
__device__ float g_qrr  [ROWS  * DM];
__device__ float g_kv   [KROWS * 2 * HD];
__device__ float g_pos  [KLEN  * DM];
__device__ float g_rk   [KLEN  * DM];
__device__ float g_sc   [(size_t)BSZ * NH * QLEN * KLEN];
__device__ float g_bd   [(size_t)NH * ROWS * KLEN];
__device__ float g_vec  [ROWS * DM];
__device__ float g_tmp  [ROWS * DM];
__device__ float g_ffh  [ROWS * DI];
__device__ float g_logit[(size_t)ROWS * NTOK];

// ---------------- helpers ----------------
__device__ __forceinline__ uint32_t f2tf32(float x) {
    uint32_t r;
    asm("cvt.rna.tf32.f32 %0, %1;" : "=r"(r) : "f"(x));
    return r;
}

__device__ __forceinline__ void mma_tf32(float* d, const uint32_t* a, const uint32_t* b) {
    asm volatile(
        "mma.sync.aligned.m16n8k8.row.col.f32.tf32.tf32.f32 "
        "{%0,%1,%2,%3}, {%4,%5,%6,%7}, {%8,%9}, {%0,%1,%2,%3};\n"
        : "+f"(d[0]), "+f"(d[1]), "+f"(d[2]), "+f"(d[3])
        : "r"(a[0]), "r"(a[1]), "r"(a[2]), "r"(a[3]), "r"(b[0]), "r"(b[1]));
}

__device__ __forceinline__ void cp16(float* sdst, const float* gsrc) {
    uint32_t s = (uint32_t)__cvta_generic_to_shared(sdst);
    asm volatile("cp.async.cg.shared.global [%0], [%1], 16;\n" :: "r"(s), "l"(gsrc));
}
#define CP_COMMIT() asm volatile("cp.async.commit_group;\n")
#define CP_WAIT1()  asm volatile("cp.async.wait_group 1;\n")

// ---------------- 3xTF32 tensor-core GEMM ----------------
// CTA tile 128xNTILE, K-step 32, 2-stage cp.async double buffer.
// NTILE=128: 512 threads, 16 warps (4x4), warp tile 32x32.
// NTILE=64 : 256 threads,  8 warps (4x2), warp tile 32x32.
// TB=0: B is KxN (NN). TB=1: B is NxK (NT).
// All dims must be exact tile multiples (true for this model): no bounds checks.
// epi: 0 none, 1 +bias, 2 relu(+bias), 3 dual-out (C=acc+bias, C2=acc+bias2)
#define APITCH 36
#define SSTR   4608

template <int TB, int NTILE>
__global__ void __launch_bounds__((NTILE == 128) ? 512 : 256)
tgemm(const float* __restrict__ A, const float* __restrict__ B, float* __restrict__ C,
      int K, int lda, int ldb, int ldc,
      long sA1, long sA2, long sB1, long sB2, long sC1, long sC2, int batch2,
      const float* __restrict__ bias, int epi,
      float* __restrict__ C2, const float* __restrict__ bias2)
{
    constexpr int THREADS = (NTILE == 128) ? 512 : 256;
    constexpr int NW_N    = NTILE / 32;           // warps along n
    constexpr int BPITCH  = (TB == 0) ? ((NTILE == 128) ? 136 : 72) : APITCH;
    constexpr int ITA     = 1024 / THREADS;       // A float4s per thread
    constexpr int ITB     = (TB == 1) ? (NTILE * 8 / THREADS) : (NTILE * 8 / THREADS);
    constexpr int NQ      = NTILE / 4;            // NN quads per k-row

    extern __shared__ float sm[];
    float* const Asm[2] = { sm,            sm + SSTR };
    float* const Bsm[2] = { sm + 2 * SSTR, sm + 3 * SSTR };

    const int bz = blockIdx.z;
    const int b1 = bz / batch2, b2 = bz % batch2;
    A += (long)b1 * sA1 + (long)b2 * sA2;
    B += (long)b1 * sB1 + (long)b2 * sB2;
    C += (long)b1 * sC1 + (long)b2 * sC2;

    const int m0 = blockIdx.y * 128;
    const int n0 = blockIdx.x * NTILE;
    const int tid = threadIdx.x;
    const int warp = tid >> 5, lane = tid & 31;
    const int wm = warp / NW_N, wn = warp % NW_N;
    const int g = lane >> 2, c = lane & 3;

    float acc[2][4][4];
#pragma unroll
    for (int mt = 0; mt < 2; mt++)
#pragma unroll
        for (int nt = 0; nt < 4; nt++)
#pragma unroll
            for (int e = 0; e < 4; e++) acc[mt][nt][e] = 0.f;

    const int KT = K >> 5;

    auto issue = [&](int kt, int stage) {
        const int k0 = kt << 5;
#pragma unroll
        for (int i = 0; i < ITA; i++) {
            const int idx = tid + i * THREADS;
            const int r = idx >> 3, q = idx & 7;
            cp16(&Asm[stage][r * APITCH + q * 4],
                 A + (long)(m0 + r) * lda + k0 + q * 4);
        }
        if (TB == 1) {
#pragma unroll
            for (int i = 0; i < ITB; i++) {
                const int idx = tid + i * THREADS;
                const int r = idx >> 3, q = idx & 7;
                cp16(&Bsm[stage][r * APITCH + q * 4],
                     B + (long)(n0 + r) * ldb + k0 + q * 4);
            }
        } else {
#pragma unroll
            for (int i = 0; i < ITB; i++) {
                const int idx = tid + i * THREADS;
                const int k = idx / NQ, q = idx % NQ;
                cp16(&Bsm[stage][k * BPITCH + q * 4],
                     B + (long)(k0 + k) * ldb + n0 + q * 4);
            }
        }
    };

    issue(0, 0); CP_COMMIT();
    if (KT > 1) issue(1, 1);
    CP_COMMIT();

    for (int kt = 0; kt < KT; kt++) {
        CP_WAIT1();
        __syncthreads();
        const float* As = Asm[kt & 1];
        const float* Bs = Bsm[kt & 1];

#pragma unroll
        for (int kb8 = 0; kb8 < 4; kb8++) {
            const int kb = kb8 * 8;
            uint32_t afh[2][4], afl[2][4], bfh[4][2], bfl[4][2];
#pragma unroll
            for (int mt = 0; mt < 2; mt++) {
                const int r0 = wm * 32 + mt * 16 + g;
                float x0 = As[r0 * APITCH + kb + c];
                float x1 = As[(r0 + 8) * APITCH + kb + c];
                float x2 = As[r0 * APITCH + kb + c + 4];
                float x3 = As[(r0 + 8) * APITCH + kb + c + 4];
                uint32_t h0 = f2tf32(x0), h1 = f2tf32(x1), h2 = f2tf32(x2), h3 = f2tf32(x3);
                afh[mt][0] = h0; afh[mt][1] = h1; afh[mt][2] = h2; afh[mt][3] = h3;
                afl[mt][0] = f2tf32(x0 - __uint_as_float(h0));
                afl[mt][1] = f2tf32(x1 - __uint_as_float(h1));
                afl[mt][2] = f2tf32(x2 - __uint_as_float(h2));
                afl[mt][3] = f2tf32(x3 - __uint_as_float(h3));
            }
#pragma unroll
            for (int nt = 0; nt < 4; nt++) {
                const int rn = wn * 32 + nt * 8 + g;
                float y0, y1;
                if (TB == 1) {
                    y0 = Bs[rn * APITCH + kb + c];
                    y1 = Bs[rn * APITCH + kb + c + 4];
                } else {
                    y0 = Bs[(kb + c) * BPITCH + rn];
                    y1 = Bs[(kb + c + 4) * BPITCH + rn];
                }
                uint32_t h0 = f2tf32(y0), h1 = f2tf32(y1);
                bfh[nt][0] = h0; bfh[nt][1] = h1;
                bfl[nt][0] = f2tf32(y0 - __uint_as_float(h0));
                bfl[nt][1] = f2tf32(y1 - __uint_as_float(h1));
            }
#pragma unroll
            for (int mt = 0; mt < 2; mt++)
#pragma unroll
                for (int nt = 0; nt < 4; nt++) {
                    mma_tf32(acc[mt][nt], afh[mt], bfh[nt]);
                    mma_tf32(acc[mt][nt], afh[mt], bfl[nt]);
                    mma_tf32(acc[mt][nt], afl[mt], bfh[nt]);
                }
        }
        __syncthreads();
        if (kt + 2 < KT) issue(kt + 2, kt & 1);
        CP_COMMIT();
    }

    // ---- epilogue (no bounds checks: exact multiples) ----
#pragma unroll
    for (int mt = 0; mt < 2; mt++) {
        const int row0 = m0 + wm * 32 + mt * 16 + g;
#pragma unroll
        for (int nt = 0; nt < 4; nt++) {
            const int col = n0 + wn * 32 + nt * 8 + c * 2;
            if (epi == 3) {
                float b0 = bias[col],  b1v = bias[col + 1];
                float d0 = bias2[col], d1v = bias2[col + 1];
#pragma unroll
                for (int half = 0; half < 2; half++) {
                    const int row = row0 + half * 8;
                    float2 o1 = { acc[mt][nt][half * 2] + b0,  acc[mt][nt][half * 2 + 1] + b1v };
                    float2 o2 = { acc[mt][nt][half * 2] + d0,  acc[mt][nt][half * 2 + 1] + d1v };
                    *(float2*)(C  + (long)row * ldc + col) = o1;
                    *(float2*)(C2 + (long)row * ldc + col) = o2;
                }
            } else {
                float b0 = 0.f, b1v = 0.f;
                if (epi >= 1) { b0 = bias[col]; b1v = bias[col + 1]; }
#pragma unroll
                for (int half = 0; half < 2; half++) {
                    const int row = row0 + half * 8;
                    float v0 = acc[mt][nt][half * 2 + 0] + b0;
                    float v1 = acc[mt][nt][half * 2 + 1] + b1v;
                    if (epi == 2) { v0 = fmaxf(v0, 0.f); v1 = fmaxf(v1, 0.f); }
                    float2 o = {v0, v1};
                    *(float2*)(C + (long)row * ldc + col) = o;
                }
            }
        }
    }
}

// ---------------- element-wise / reduction kernels ----------------

__global__ void embed_kernel(const int* __restrict__ data, const float* __restrict__ embW,
                             float* __restrict__ core)
{
    long idx = (long)blockIdx.x * 256 + threadIdx.x;
    if (idx >= (long)ROWS * DM) return;
    int r = (int)(idx >> 10), d = (int)(idx & 1023);
    core[idx] = embW[(long)data[r] * DM + d];
}

__global__ void pos_kernel(float* __restrict__ pos)
{
    long idx = (long)blockIdx.x * 256 + threadIdx.x;
    if (idx >= (long)KLEN * DM) return;
    int j = (int)(idx >> 10), d = (int)(idx & 1023);
    float p = (float)(KLEN - 1 - j);
    int t = (d < 512) ? d : d - 512;
    float invf = expf(-((2.0f * (float)t) / (float)DM) * logf(10000.0f));
    float a = p * invf;
    pos[idx] = (d < 512) ? sinf(a) : cosf(a);
}

__global__ void attn_softmax_kernel(float* __restrict__ sc, const float* __restrict__ bd)
{
    const int i = blockIdx.x, n = blockIdx.y, b = blockIdx.z;
    const int t = threadIdx.x;
    float* row = sc + ((((long)b * NH + n) * QLEN + i) * KLEN);
    const float* bdr = bd + (((long)n * ROWS + (i * BSZ + b)) * KLEN);
    const int limit = i + MEMLEN;
    const int shift = QLEN - 1 - i;

    __shared__ float red[256];
    float v[4];
    float m = -1e30f;
#pragma unroll
    for (int k = 0; k < 4; k++) {
        int j = t + k * 256;
        float x = -1e30f;
        if (j <= limit) x = (row[j] + bdr[j + shift]) * SCALE;
        v[k] = x;
        m = fmaxf(m, x);
    }
    red[t] = m; __syncthreads();
    for (int o = 128; o > 0; o >>= 1) { if (t < o) red[t] = fmaxf(red[t], red[t + o]); __syncthreads(); }
    const float M = red[0];
    __syncthreads();

    float s = 0.f;
#pragma unroll
    for (int k = 0; k < 4; k++) { float e = expf(v[k] - M); v[k] = e; s += e; }
    red[t] = s; __syncthreads();
    for (int o = 128; o > 0; o >>= 1) { if (t < o) red[t] += red[t + o]; __syncthreads(); }
    const float inv = 1.0f / red[0];
#pragma unroll
    for (int k = 0; k < 4; k++) row[t + k * 256] = v[k] * inv;
}

__global__ void ln_kernel(const float* __restrict__ x, const float* __restrict__ y,
                          const float* __restrict__ g, const float* __restrict__ b,
                          float* __restrict__ out)
{
    const int r = blockIdx.x, t = threadIdx.x;
    __shared__ float red[256];
    const float* xr = x + (long)r * DM;
    const float* yr = y + (long)r * DM;
    float loc[4];
    float s = 0.f;
#pragma unroll
    for (int k = 0; k < 4; k++) { float v = xr[t + k * 256] + yr[t + k * 256]; loc[k] = v; s += v; }
    red[t] = s; __syncthreads();
    for (int o = 128; o > 0; o >>= 1) { if (t < o) red[t] += red[t + o]; __syncthreads(); }
    const float mu = red[0] * (1.0f / DM);
    __syncthreads();
    float s2 = 0.f;
#pragma unroll
    for (int k = 0; k < 4; k++) { float d = loc[k] - mu; s2 += d * d; }
    red[t] = s2; __syncthreads();
    for (int o = 128; o > 0; o >>= 1) { if (t < o) red[t] += red[t + o]; __syncthreads(); }
    const float rstd = rsqrtf(red[0] * (1.0f / DM) + 1e-5f);
#pragma unroll
    for (int k = 0; k < 4; k++) {
        int d = t + k * 256;
        out[(long)r * DM + d] = (loc[k] - mu) * rstd * g[d] + b[d];
    }
}

// single-pass online logsumexp loss
__global__ void loss_kernel(const float* __restrict__ logits, const int* __restrict__ target,
                            float* __restrict__ out)
{
    const int r = blockIdx.x, t = threadIdx.x;
    __shared__ float rm[256], rs[256];
    const float* lr = logits + (long)r * NTOK;
    float m = -1e30f, s = 0.f;
    for (int j = t; j < NTOK; j += 256) {
        float x = lr[j];
        if (x > m) { s = s * expf(m - x) + 1.f; m = x; }
        else       { s += expf(x - m); }
    }
    rm[t] = m; rs[t] = s; __syncthreads();
    for (int o = 128; o > 0; o >>= 1) {
        if (t < o) {
            float m2 = rm[t + o], s2 = rs[t + o];
            float M = fmaxf(rm[t], m2);
            rs[t] = rs[t] * expf(rm[t] - M) + s2 * expf(m2 - M);
            rm[t] = M;
        }
        __syncthreads();
    }
    if (t == 0) out[r] = (logf(rs[0]) + rm[0]) - lr[target[r]];
}

// ---------------- host orchestration ----------------

#define SMEM_GEMM (4 * SSTR * 4)   // 73728 bytes

static inline dim3 gt(int N, int M, int bz, int ntile) {
    return dim3(N / ntile, M / 128, bz);
}

extern "C" void kernel_launch(void* const* d_in, const int* in_sizes, int n_in,
                              void* d_out, int out_size)
{
    const int*   data   = (const int*)  d_in[0];
    const int*   target = (const int*)  d_in[1];
    const float* memory = (const float*)d_in[2];
    const float* embW   = (const float*)d_in[3];
    const float* rwb    = (const float*)d_in[4];
    const float* rrb    = (const float*)d_in[5];
    const float* Wq     = (const float*)d_in[6];
    const float* Wkv    = (const float*)d_in[7];
    const float* Wr     = (const float*)d_in[8];
    const float* Wo     = (const float*)d_in[9];
    const float* W1     = (const float*)d_in[10];
    const float* b1     = (const float*)d_in[11];
    const float* W2     = (const float*)d_in[12];
    const float* b2     = (const float*)d_in[13];
    const float* ln1g   = (const float*)d_in[14];
    const float* ln1b   = (const float*)d_in[15];
    const float* ln2g   = (const float*)d_in[16];
    const float* ln2b   = (const float*)d_in[17];

    float* out      = (float*)d_out;
    float* out_loss = out;
    float* out_mems = out + ROWS;

    float *core, *qrw, *qrr, *kv, *pos, *rk, *sc, *bd, *vec, *tmp, *ffh, *logit;
    cudaGetSymbolAddress((void**)&core,  g_core);
    cudaGetSymbolAddress((void**)&qrw,   g_qrw);
    cudaGetSymbolAddress((void**)&qrr,   g_qrr);
    cudaGetSymbolAddress((void**)&kv,    g_kv);
    cudaGetSymbolAddress((void**)&pos,   g_pos);
    cudaGetSymbolAddress((void**)&rk,    g_rk);
    cudaGetSymbolAddress((void**)&sc,    g_sc);
    cudaGetSymbolAddress((void**)&bd,    g_bd);
    cudaGetSymbolAddress((void**)&vec,   g_vec);
    cudaGetSymbolAddress((void**)&tmp,   g_tmp);
    cudaGetSymbolAddress((void**)&ffh,   g_ffh);
    cudaGetSymbolAddress((void**)&logit, g_logit);

    cudaFuncSetAttribute(tgemm<0,128>, cudaFuncAttributeMaxDynamicSharedMemorySize, SMEM_GEMM);
    cudaFuncSetAttribute(tgemm<1,128>, cudaFuncAttributeMaxDynamicSharedMemorySize, SMEM_GEMM);
    cudaFuncSetAttribute(tgemm<0,64>,  cudaFuncAttributeMaxDynamicSharedMemorySize, SMEM_GEMM);

    const size_t coreBytes = (size_t)ROWS * DM * sizeof(float);

    embed_kernel<<<(ROWS * DM + 255) / 256, 256>>>(data, embW, core);
    pos_kernel  <<<(KLEN * DM + 255) / 256, 256>>>(pos);

    cudaMemcpyAsync(out_mems, core, coreBytes, cudaMemcpyDeviceToDevice);

    for (int l = 0; l < NL; l++) {
        const float* Wkvl = Wkv + (size_t)l * DM * 2 * HD;

        // kv rows [0,4096): from memory[l];  rows [4096,8192): from core
        tgemm<0,128><<<gt(2*HD, ROWS, 1, 128), 512, SMEM_GEMM>>>(
            memory + (size_t)l * ROWS * DM, Wkvl, kv,
            DM, DM, 2*HD, 2*HD, 0,0,0,0,0,0, 1, nullptr, 0, nullptr, nullptr);
        tgemm<0,128><<<gt(2*HD, ROWS, 1, 128), 512, SMEM_GEMM>>>(
            core, Wkvl, kv + (size_t)ROWS * 2 * HD,
            DM, DM, 2*HD, 2*HD, 0,0,0,0,0,0, 1, nullptr, 0, nullptr, nullptr);

        // qrw / qrr = core @ Wq + {rwb, rrb}  (dual-output epilogue)
        tgemm<0,128><<<gt(HD, ROWS, 1, 128), 512, SMEM_GEMM>>>(
            core, Wq + (size_t)l * DM * HD, qrw,
            DM, DM, HD, HD, 0,0,0,0,0,0, 1, rwb, 3, qrr, rrb);

        // r_k = pos @ Wr
        tgemm<0,128><<<gt(HD, KLEN, 1, 128), 512, SMEM_GEMM>>>(
            pos, Wr + (size_t)l * DM * HD, rk,
            DM, DM, HD, HD, 0,0,0,0,0,0, 1, nullptr, 0, nullptr, nullptr);

        // AC (NT, batched over b*n)
        tgemm<1,128><<<gt(KLEN, QLEN, BSZ*NH, 128), 512, SMEM_GEMM>>>(
            qrw, kv, sc,
            DH, BSZ * DM, BSZ * 2 * HD, KLEN,
            (long)DM, (long)DH,
            (long)2 * HD, (long)DH,
            (long)NH * QLEN * KLEN, (long)QLEN * KLEN,
            NH, nullptr, 0, nullptr, nullptr);

        // BD raw (NT, batched over n)
        tgemm<1,128><<<gt(KLEN, ROWS, NH, 128), 512, SMEM_GEMM>>>(
            qrr, rk, bd,
            DH, DM, DM, KLEN,
            0, (long)DH,
            0, (long)DH,
            0, (long)ROWS * KLEN,
            NH, nullptr, 0, nullptr, nullptr);

        attn_softmax_kernel<<<dim3(QLEN, NH, BSZ), 256>>>(sc, bd);

        // PV (NN, N=64 tiles, batched over b*n)
        tgemm<0,64><<<gt(DH, QLEN, BSZ*NH, 64), 256, SMEM_GEMM>>>(
            sc, kv + HD, vec,
            KLEN, KLEN, BSZ * 2 * HD, BSZ * DM,
            (long)NH * QLEN * KLEN, (long)QLEN * KLEN,
            (long)2 * HD, (long)DH,
            (long)DM, (long)DH,
            NH, nullptr, 0, nullptr, nullptr);

        // attn_out = vec @ Wo
        tgemm<0,128><<<gt(DM, ROWS, 1, 128), 512, SMEM_GEMM>>>(
            vec, Wo + (size_t)l * HD * DM, tmp,
            HD, HD, DM, DM, 0,0,0,0,0,0, 1, nullptr, 0, nullptr, nullptr);
        ln_kernel<<<ROWS, 256>>>(core, tmp, ln1g + (size_t)l * DM, ln1b + (size_t)l * DM, core);

        // ffh = relu(core @ W1 + b1)
        tgemm<0,128><<<gt(DI, ROWS, 1, 128), 512, SMEM_GEMM>>>(
            core, W1 + (size_t)l * DM * DI, ffh,
            DM, DM, DI, DI, 0,0,0,0,0,0, 1, b1 + (size_t)l * DI, 2, nullptr, nullptr);
        // ff_out = ffh @ W2 + b2
        tgemm<0,128><<<gt(DM, ROWS, 1, 128), 512, SMEM_GEMM>>>(
            ffh, W2 + (size_t)l * DI * DM, tmp,
            DI, DI, DM, DM, 0,0,0,0,0,0, 1, b2 + (size_t)l * DM, 1, nullptr, nullptr);
        ln_kernel<<<ROWS, 256>>>(core, tmp, ln2g + (size_t)l * DM, ln2b + (size_t)l * DM, core);

        if (l < NL - 1)
            cudaMemcpyAsync(out_mems + (size_t)(l + 1) * ROWS * DM, core, coreBytes,
                            cudaMemcpyDeviceToDevice);
    }

    // logits = core @ emb_W^T
    tgemm<1,128><<<gt(NTOK, ROWS, 1, 128), 512, SMEM_GEMM>>>(
        core, embW, logit,
        DM, DM, DM, NTOK, 0,0,0,0,0,0, 1, nullptr, 0, nullptr, nullptr);
    loss_kernel<<<ROWS, 256>>>(logit, target, out_loss);

    (void)in_sizes; (void)n_in; (void)out_size;
}